// round 5
// baseline (speedup 1.0000x reference)
#include <cuda_runtime.h>
#include <cuda_bf16.h>

// FuzzyLayer: out[b,s,d*I+i] = exp(-(x[b,s,i]-mu[d,i])^2 / sigma[d,i])
// B=16, S=2048, I=256, D=8.  256 MB write + 32 MB read -> HBM-write-bound.
//
// R4 -> R5 change: the fill->barrier->store serialization was the remaining
// exposure. Now: persistent blocks (grid = 148*4 = 592, one full wave at
// 4 CTAs/SM) iterate over 16-row tiles, double-buffered in SMEM via
// cp.async — the next tile's x fill runs UNDER the current tile's 128 KB
// store burst. No store-silent windows after the prologue; no wave tail.
// Kept: thread owns fixed output column group (poly coeffs in regs:
// exp2((a*x+b)*x+e)), all 8 'd' groups co-resident, float4 traffic,
// __stcs streaming stores.

static constexpr int BS     = 16 * 2048;       // 32768 rows
static constexpr int TROWS  = 16;              // rows per tile
static constexpr int NTILES = BS / TROWS;      // 2048 tiles
static constexpr int GRID   = 148 * 4;         // 592 blocks = one full wave

__device__ __forceinline__ float ex2_approx(float t) {
    float r;
    asm("ex2.approx.ftz.f32 %0, %1;" : "=f"(r) : "f"(t));
    return r;
}

__global__ void __launch_bounds__(512, 4)
fuzzy_kernel(const float4* __restrict__ x4,
             const float4* __restrict__ fp4,
             float4* __restrict__ out4)
{
    __shared__ float4 sx[2][TROWS * 64];        // 2 x 16 KB double buffer

    const int tid = threadIdx.x;
    const int i4  = tid & 63;                   // float4 group within I
    const int d   = tid >> 6;                   // fuzzy degree

    // fuzzy_params (2048,2) row-major: fp[2j]=mu_j, fp[2j+1]=sigma_j, j=d*256+i.
    const float4 p0 = fp4[d * 128 + i4 * 2];
    const float4 p1 = fp4[d * 128 + i4 * 2 + 1];

    const float L2E = 1.4426950408889634f;
    // exponent(x) = rs*(x-mu)^2 = (a*x + b)*x + e
    const float a0 = -L2E / p0.y, b0 = -2.f * a0 * p0.x, e0 = a0 * p0.x * p0.x;
    const float a1 = -L2E / p0.w, b1 = -2.f * a1 * p0.z, e1 = a1 * p0.z * p0.z;
    const float a2 = -L2E / p1.y, b2 = -2.f * a2 * p1.x, e2 = a2 * p1.x * p1.x;
    const float a3 = -L2E / p1.w, b3 = -2.f * a3 * p1.z, e3 = a3 * p1.z * p1.z;

    // Per-tile fill: TROWS*64 = 1024 float4 over 512 threads = 2 x 16B cp.async.
    auto prefetch = [&](int buf, int t) {
        const float4* src = x4 + (size_t)t * TROWS * 64 + tid;
        unsigned saddr = (unsigned)__cvta_generic_to_shared(&sx[buf][tid]);
#pragma unroll
        for (int k = 0; k < 2; ++k) {
            asm volatile("cp.async.cg.shared.global [%0], [%1], 16;"
                         :: "r"(saddr + k * 512 * 16), "l"(src + k * 512));
        }
        asm volatile("cp.async.commit_group;");
    };

    int t   = blockIdx.x;
    int buf = 0;
    prefetch(0, t);                              // prologue fill

    for (; t < NTILES; t += GRID) {
        asm volatile("cp.async.wait_group 0;" ::: "memory");
        __syncthreads();                         // current buffer fully resident
                                                 // + all warps done with prev buffer

        const int tn = t + GRID;
        if (tn < NTILES) prefetch(buf ^ 1, tn);  // next fill runs under stores

        float4* __restrict__ oout = out4 + (size_t)t * TROWS * 512 + tid;
        const float4* __restrict__ sb = &sx[buf][i4];

#pragma unroll 4
        for (int r = 0; r < TROWS; ++r) {
            const float4 xv = sb[r * 64];
            float4 o;
            o.x = ex2_approx(fmaf(fmaf(a0, xv.x, b0), xv.x, e0));
            o.y = ex2_approx(fmaf(fmaf(a1, xv.y, b1), xv.y, e1));
            o.z = ex2_approx(fmaf(fmaf(a2, xv.z, b2), xv.z, e2));
            o.w = ex2_approx(fmaf(fmaf(a3, xv.w, b3), xv.w, e3));
            __stcs(oout + r * 512, o);
        }
        buf ^= 1;
    }
}

extern "C" void kernel_launch(void* const* d_in, const int* in_sizes, int n_in,
                              void* d_out, int out_size)
{
    const float4* x4  = (const float4*)d_in[0];   // x: (16,2048,256) f32
    const float4* fp4 = (const float4*)d_in[1];   // fuzzy_params: (2048,2) f32
    float4* out4      = (float4*)d_out;           // (16,2048,2048) f32

    fuzzy_kernel<<<GRID, 512>>>(x4, fp4, out4);
}

// round 6
// speedup vs baseline: 1.0343x; 1.0343x over previous
#include <cuda_runtime.h>
#include <cuda_bf16.h>

// FuzzyLayer: out[b,s,d*I+i] = exp(-(x[b,s,i]-mu[d,i])^2 / sigma[d,i])
// B=16, S=2048, I=256, D=8.  256 MB write + 32 MB read -> HBM-write-bound.
//
// R5 -> R6: R5's persistent single-wave pipeline regressed (phase-locked
// fills, no desync, 3.5 iters/block). Revert to R4's structure (1024 short
// blocks, 32-row tile, single-shot) and hide the fill INSIDE it:
//  - x fill issued as 4 cp.async commit-groups of 8 rows each, up front.
//  - chunk c: wait_group(3-c) + syncthreads + compute/store 8 rows.
//    -> only the first 8 KB of fill is latency-exposed; chunks 1-3 stream
//    in under the store bursts of chunks 0-2.
// Kept: thread owns fixed output column group (poly coeffs in regs:
// exp2((a*x+b)*x+e)), all 8 'd' groups co-resident, float4 traffic,
// __stcs streaming stores, __launch_bounds__(512,4).

static constexpr int BS    = 16 * 2048;     // 32768 rows
static constexpr int ROWS  = 32;            // rows per block
static constexpr int CHUNK = 8;             // rows per cp.async group
static constexpr int NCHUNK = ROWS / CHUNK; // 4

__device__ __forceinline__ float ex2_approx(float t) {
    float r;
    asm("ex2.approx.ftz.f32 %0, %1;" : "=f"(r) : "f"(t));
    return r;
}

template <int N>
__device__ __forceinline__ void cp_async_wait_group() {
    asm volatile("cp.async.wait_group %0;" :: "n"(N) : "memory");
}

__global__ void __launch_bounds__(512, 4)
fuzzy_kernel(const float4* __restrict__ x4,
             const float4* __restrict__ fp4,
             float4* __restrict__ out4)
{
    __shared__ float4 sx[ROWS * 64];         // 32 KB

    const int tid = threadIdx.x;
    const int i4  = tid & 63;                // float4 group within I
    const int d   = tid >> 6;                // fuzzy degree

    // fuzzy_params (2048,2) row-major: fp[2j]=mu_j, fp[2j+1]=sigma_j, j=d*256+i.
    const float4 p0 = fp4[d * 128 + i4 * 2];
    const float4 p1 = fp4[d * 128 + i4 * 2 + 1];

    const float L2E = 1.4426950408889634f;
    // exponent(x) = rs*(x-mu)^2 = (a*x + b)*x + e
    const float a0 = -L2E / p0.y, b0 = -2.f * a0 * p0.x, e0 = a0 * p0.x * p0.x;
    const float a1 = -L2E / p0.w, b1 = -2.f * a1 * p0.z, e1 = a1 * p0.z * p0.z;
    const float a2 = -L2E / p1.y, b2 = -2.f * a2 * p1.x, e2 = a2 * p1.x * p1.x;
    const float a3 = -L2E / p1.w, b3 = -2.f * a3 * p1.z, e3 = a3 * p1.z * p1.z;

    const int bs0 = blockIdx.x * ROWS;

    // Issue all 4 chunk fills up front (1 cp.async.16B per thread per chunk).
    {
        const float4* src = x4 + (size_t)bs0 * 64 + tid;
        unsigned sbase = (unsigned)__cvta_generic_to_shared(&sx[tid]);
#pragma unroll
        for (int c = 0; c < NCHUNK; ++c) {
            asm volatile("cp.async.cg.shared.global [%0], [%1], 16;"
                         :: "r"(sbase + c * 512 * 16), "l"(src + c * 512));
            asm volatile("cp.async.commit_group;");
        }
    }

    float4* __restrict__ oout = out4 + (size_t)bs0 * 512 + tid;

    // Chunk c becomes consumable when 3-c groups may remain outstanding.
#pragma unroll
    for (int c = 0; c < NCHUNK; ++c) {
        if (c == 0) cp_async_wait_group<3>();
        else if (c == 1) cp_async_wait_group<2>();
        else if (c == 2) cp_async_wait_group<1>();
        else cp_async_wait_group<0>();
        __syncthreads();

#pragma unroll
        for (int r = c * CHUNK; r < (c + 1) * CHUNK; ++r) {
            const float4 xv = sx[r * 64 + i4];
            float4 o;
            o.x = ex2_approx(fmaf(fmaf(a0, xv.x, b0), xv.x, e0));
            o.y = ex2_approx(fmaf(fmaf(a1, xv.y, b1), xv.y, e1));
            o.z = ex2_approx(fmaf(fmaf(a2, xv.z, b2), xv.z, e2));
            o.w = ex2_approx(fmaf(fmaf(a3, xv.w, b3), xv.w, e3));
            __stcs(oout + r * 512, o);
        }
    }
}

extern "C" void kernel_launch(void* const* d_in, const int* in_sizes, int n_in,
                              void* d_out, int out_size)
{
    const float4* x4  = (const float4*)d_in[0];   // x: (16,2048,256) f32
    const float4* fp4 = (const float4*)d_in[1];   // fuzzy_params: (2048,2) f32
    float4* out4      = (float4*)d_out;           // (16,2048,2048) f32

    fuzzy_kernel<<<BS / ROWS, 512>>>(x4, fp4, out4);   // 1024 blocks
}